// round 1
// baseline (speedup 1.0000x reference)
#include <cuda_runtime.h>
#include <cstdint>

#define DIM    512
#define NE     4096
#define NROWS  65536   // B*T = 16*4096

// ---- scratch (no allocations allowed) ----
__device__ float g_embT[NE * DIM];     // embed transposed: [NE][DIM], 8MB
__device__ float g_e2[NE];             // ||e_j||^2
__device__ int   g_best[NROWS];        // argmin index per row
__device__ float g_partial[NROWS];     // per-row squared-diff sums

// ============================================================
// Kernel 1a: transpose embed [DIM][NE] -> embT [NE][DIM]
// ============================================================
__global__ void prep_transpose(const float* __restrict__ embed) {
    __shared__ float tile[32][33];
    int jb = blockIdx.x * 32;  // along NE
    int db = blockIdx.y * 32;  // along DIM
    int tx = threadIdx.x, ty = threadIdx.y;  // 32 x 8
    #pragma unroll
    for (int d = ty; d < 32; d += 8)
        tile[d][tx] = embed[(size_t)(db + d) * NE + jb + tx];
    __syncthreads();
    #pragma unroll
    for (int j = ty; j < 32; j += 8)
        g_embT[(size_t)(jb + j) * DIM + db + tx] = tile[tx][j];
}

// ============================================================
// Kernel 1b: e2[j] = sum_d embed[d][j]^2
// ============================================================
__global__ void prep_e2(const float* __restrict__ embed) {
    int j = blockIdx.x * blockDim.x + threadIdx.x;
    if (j < NE) {
        float s = 0.f;
        #pragma unroll 8
        for (int d = 0; d < DIM; d++) {
            float v = embed[(size_t)d * NE + j];
            s = fmaf(v, v, s);
        }
        g_e2[j] = s;
    }
}

// ============================================================
// Kernel 2: fused GEMM + argmin.
// dist_j = e2[j] - 2 * f.e_j   (row-constant ||f||^2 dropped)
// CTA tile: 128 rows x 128 cols, BK=16, 8x8 per thread, 256 threads.
// ============================================================
#define BM 128
#define BN 128
#define BK 16
#define TM 8
#define TN 8

__global__ __launch_bounds__(256) void argmin_kernel(
    const float* __restrict__ x, const float* __restrict__ embed)
{
    __shared__ float As[BK][BM + 4];
    __shared__ float Bs[BK][BN + 4];
    __shared__ float redv[BM][17];
    __shared__ int   redi[BM][17];

    const int t  = threadIdx.x;
    const int tx = t & 15;       // 0..15 -> cols
    const int ty = t >> 4;       // 0..15 -> rows
    const int row0 = blockIdx.x * BM;
    const float* xrow = x + (size_t)row0 * DIM;

    float bv[TM];
    int   bi[TM];
    #pragma unroll
    for (int i = 0; i < TM; i++) { bv[i] = 3.4e38f; bi[i] = 0; }

    for (int col0 = 0; col0 < NE; col0 += BN) {
        float acc[TM][TN];
        #pragma unroll
        for (int i = 0; i < TM; i++)
            #pragma unroll
            for (int j = 0; j < TN; j++) acc[i][j] = 0.f;

        for (int k0 = 0; k0 < DIM; k0 += BK) {
            // Load A tile (x): 128 rows x 16 k, transposed into As[k][row]
            #pragma unroll
            for (int qq = 0; qq < 2; qq++) {
                int q  = t + qq * 256;     // 0..511 float4 slots
                int k4 = q & 3;            // which float4 within 16-k row chunk
                int r  = q >> 2;           // row 0..127
                float4 v = *(const float4*)(xrow + (size_t)r * DIM + k0 + k4 * 4);
                As[k4 * 4 + 0][r] = v.x;
                As[k4 * 4 + 1][r] = v.y;
                As[k4 * 4 + 2][r] = v.z;
                As[k4 * 4 + 3][r] = v.w;
            }
            // Load B tile (embed): 16 k x 128 cols, direct
            #pragma unroll
            for (int qq = 0; qq < 2; qq++) {
                int q  = t + qq * 256;
                int k  = q >> 5;           // 0..15
                int c4 = q & 31;           // 0..31 float4 across 128 cols
                float4 v = *(const float4*)(embed + (size_t)(k0 + k) * NE + col0 + c4 * 4);
                *(float4*)&Bs[k][c4 * 4] = v;
            }
            __syncthreads();

            #pragma unroll
            for (int k = 0; k < BK; k++) {
                float a[TM], b[TN];
                float4 a0 = *(const float4*)&As[k][ty * 8];
                float4 a1 = *(const float4*)&As[k][ty * 8 + 4];
                float4 b0 = *(const float4*)&Bs[k][tx * 8];
                float4 b1 = *(const float4*)&Bs[k][tx * 8 + 4];
                a[0]=a0.x; a[1]=a0.y; a[2]=a0.z; a[3]=a0.w;
                a[4]=a1.x; a[5]=a1.y; a[6]=a1.z; a[7]=a1.w;
                b[0]=b0.x; b[1]=b0.y; b[2]=b0.z; b[3]=b0.w;
                b[4]=b1.x; b[5]=b1.y; b[6]=b1.z; b[7]=b1.w;
                #pragma unroll
                for (int i = 0; i < TM; i++)
                    #pragma unroll
                    for (int j = 0; j < TN; j++)
                        acc[i][j] = fmaf(a[i], b[j], acc[i][j]);
            }
            __syncthreads();
        }

        // epilogue: dist = e2 - 2*dot, running argmin (ascending cols -> strict <)
        #pragma unroll
        for (int j = 0; j < TN; j++) {
            int col = col0 + tx * 8 + j;
            float e2 = __ldg(&g_e2[col]);
            #pragma unroll
            for (int i = 0; i < TM; i++) {
                float d = fmaf(-2.f, acc[i][j], e2);
                if (d < bv[i]) { bv[i] = d; bi[i] = col; }
            }
        }
    }

    // cross-thread reduction (16 col-threads per row), tie -> lower index
    #pragma unroll
    for (int i = 0; i < TM; i++) {
        redv[ty * 8 + i][tx] = bv[i];
        redi[ty * 8 + i][tx] = bi[i];
    }
    __syncthreads();
    if (t < BM) {
        float best = redv[t][0];
        int  besti = redi[t][0];
        #pragma unroll
        for (int j = 1; j < 16; j++) {
            float v = redv[t][j];
            int  idx = redi[t][j];
            if (v < best || (v == best && idx < besti)) { best = v; besti = idx; }
        }
        g_best[row0 + t] = besti;
    }
}

// ============================================================
// Kernel 3: gather quantize (coalesced via embT), squared-diff
// partials, embed_ind as float. One block (128 thr) per row.
// ============================================================
__global__ __launch_bounds__(128) void gather_kernel(
    const float* __restrict__ x, float* __restrict__ out)
{
    const int row = blockIdx.x;
    const int t = threadIdx.x;
    const int idx = g_best[row];
    const float4* q4 = (const float4*)(g_embT + (size_t)idx * DIM);
    const float4* x4 = (const float4*)(x + (size_t)row * DIM);
    float4* o4 = (float4*)(out + (size_t)row * DIM);

    float4 q = q4[t];
    float4 xv = x4[t];
    // straight-through: x + (q - x), matching reference rounding
    float dx = q.x - xv.x, dy = q.y - xv.y, dz = q.z - xv.z, dw = q.w - xv.w;
    float4 o;
    o.x = xv.x + dx; o.y = xv.y + dy; o.z = xv.z + dz; o.w = xv.w + dw;
    o4[t] = o;
    float s = dx * dx + dy * dy + dz * dz + dw * dw;

    __shared__ float red[128];
    red[t] = s;
    __syncthreads();
    #pragma unroll
    for (int off = 64; off > 0; off >>= 1) {
        if (t < off) red[t] += red[t + off];
        __syncthreads();
    }
    if (t == 0) {
        g_partial[row] = red[0];
        // layout: [quantize (NROWS*DIM)] [diff (1)] [embed_ind (NROWS)]
        out[(size_t)NROWS * DIM + 1 + row] = (float)idx;
    }
}

// ============================================================
// Kernel 4: deterministic final reduction -> diff scalar
// ============================================================
__global__ void final_kernel(float* __restrict__ out) {
    __shared__ double red[256];
    int t = threadIdx.x;
    double s = 0.0;
    for (int i = t; i < NROWS; i += 256) s += (double)g_partial[i];
    red[t] = s;
    __syncthreads();
    for (int off = 128; off > 0; off >>= 1) {
        if (t < off) red[t] += red[t + off];
        __syncthreads();
    }
    if (t == 0)
        out[(size_t)NROWS * DIM] = (float)(red[0] / ((double)NROWS * (double)DIM));
}

// ============================================================
extern "C" void kernel_launch(void* const* d_in, const int* in_sizes, int n_in,
                              void* d_out, int out_size) {
    const float* x     = (const float*)d_in[0];   // [16,4096,512] fp32
    const float* embed = (const float*)d_in[1];   // [512,4096] fp32
    float* out = (float*)d_out;

    dim3 tgrid(NE / 32, DIM / 32);
    dim3 tblk(32, 8);
    prep_transpose<<<tgrid, tblk>>>(embed);
    prep_e2<<<NE / 256, 256>>>(embed);
    argmin_kernel<<<NROWS / BM, 256>>>(x, embed);
    gather_kernel<<<NROWS, 128>>>(x, out);
    final_kernel<<<1, 256>>>(out);
}

// round 6
// speedup vs baseline: 2.4780x; 2.4780x over previous
#include <cuda_runtime.h>
#include <cuda_fp16.h>
#include <cstdint>
#include <cfloat>

#define DIM    512
#define NE     4096
#define NROWS  65536
#define THRESH 0.35f

// ---------------- scratch (__device__ globals) ----------------
__device__ __align__(128) __half g_Ah[(size_t)NROWS * DIM];  // x as fp16
__device__ __align__(128) __half g_Bh[(size_t)NE * DIM];     // embT as fp16
__device__ float g_embT[(size_t)NE * DIM];
__device__ float g_e2[NE];
__device__ int   g_best[NROWS];
__device__ float g_margin[NROWS];
__device__ float g_partial[NROWS];
__device__ int   g_list[NROWS];
__device__ int   g_cnt;

// ---------------- asm helpers (all sm_80-era, valid in sm_100 PTX) --------
__device__ __forceinline__ uint32_t smem_u32(const void* p) {
    uint32_t a;
    asm("{ .reg .u64 t; cvta.to.shared.u64 t, %1; cvt.u32.u64 %0, t; }" : "=r"(a) : "l"(p));
    return a;
}
#define CP16(dst, src) \
    asm volatile("cp.async.cg.shared.global [%0], [%1], 16;" :: "r"(dst), "l"(src))
#define CP_COMMIT() asm volatile("cp.async.commit_group;" ::: "memory")

#define LDSM4(r, addr) \
    asm volatile("ldmatrix.sync.aligned.m8n8.x4.shared.b16 {%0,%1,%2,%3}, [%4];" \
        : "=r"((r)[0]), "=r"((r)[1]), "=r"((r)[2]), "=r"((r)[3]) : "r"(addr))

#define MMA16(c, a, b0, b1) \
    asm volatile("mma.sync.aligned.m16n8k16.row.col.f32.f16.f16.f32 " \
        "{%0,%1,%2,%3},{%4,%5,%6,%7},{%8,%9},{%0,%1,%2,%3};" \
        : "+f"((c)[0]), "+f"((c)[1]), "+f"((c)[2]), "+f"((c)[3]) \
        : "r"((a)[0]), "r"((a)[1]), "r"((a)[2]), "r"((a)[3]), "r"(b0), "r"(b1))

// ---------------- prep: pack x -> fp16 ----------------
__global__ __launch_bounds__(256) void pack_x_kernel(const float* __restrict__ x) {
    size_t g = (size_t)blockIdx.x * 256 + threadIdx.x;
    if (g == 0) g_cnt = 0;
    size_t e = g * 4;
    float4 v = *(const float4*)(x + e);
    __half2 h0 = __floats2half2_rn(v.x, v.y);
    __half2 h1 = __floats2half2_rn(v.z, v.w);
    uint2 pk;
    pk.x = *(uint32_t*)&h0;
    pk.y = *(uint32_t*)&h1;
    *(uint2*)(g_Ah + e) = pk;
}

// ---------------- prep: transpose embed -> fp16 B + fp32 embT ----------------
__global__ void pack_embed_kernel(const float* __restrict__ embed) {
    __shared__ float tile[32][33];
    int jb = blockIdx.x * 32;
    int db = blockIdx.y * 32;
    int tx = threadIdx.x, ty = threadIdx.y;  // 32 x 8
    #pragma unroll
    for (int d = ty; d < 32; d += 8)
        tile[d][tx] = embed[(size_t)(db + d) * NE + jb + tx];
    __syncthreads();
    #pragma unroll
    for (int j = ty; j < 32; j += 8) {
        float v = tile[tx][j];
        size_t o = (size_t)(jb + j) * DIM + db + tx;
        g_Bh[o]   = __float2half_rn(v);
        g_embT[o] = v;
    }
}

__global__ void prep_e2(const float* __restrict__ embed) {
    int j = blockIdx.x * blockDim.x + threadIdx.x;
    if (j < NE) {
        float s = 0.f;
        #pragma unroll 8
        for (int d = 0; d < DIM; d++) {
            float v = embed[(size_t)d * NE + j];
            s = fmaf(v, v, s);
        }
        g_e2[j] = s;
    }
}

// ---------------- GEMM + argmin (mma.sync fp16, A resident in SMEM) --------
// SMEM layout (dynamic, 212992 B total):
//   [0, 131072)        A block 128 x 512 fp16, swizzled
//   [131072, 196608)   B stages: 4 x 16384 (128n x 64k fp16, swizzled)
//                      (reused post-loop as merge buffer)
//   [196608, 212992)   e2[4096] fp32
#define SA_OFF 0
#define SB_OFF 131072
#define SE_OFF 196608
#define SMEM_SZ 212992

__device__ __forceinline__ void load_B(uint32_t sB, int t, int slot, int idx) {
    const int col0 = (idx >> 3) << 7;
    const int kk = idx & 7;
    const __half* base = g_Bh + (size_t)col0 * DIM + kk * 64;
    uint32_t sbase = sB + slot * 16384;
    #pragma unroll
    for (int i = 0; i < 4; i++) {
        int q = t + i * 256;
        int n = q >> 3, ck = q & 7;
        uint32_t dst = sbase + n * 128 + (((ck ^ (n & 7))) << 4);
        const __half* src = base + (size_t)n * DIM + ck * 8;
        CP16(dst, src);
    }
}

__global__ __launch_bounds__(256, 1) void gemm_argmin_kernel() {
    extern __shared__ __align__(128) char smem[];
    const uint32_t sbase = smem_u32(smem);
    const uint32_t sA = sbase + SA_OFF;
    const uint32_t sB = sbase + SB_OFF;
    const int t = threadIdx.x;
    const int lane = t & 31, warp = t >> 5;
    const int wr = warp >> 2, wc = warp & 3;      // 2 x 4 warp grid
    const int row0 = blockIdx.x * 128;
    float* e2p = (float*)(smem + SE_OFF);

    // ---- group 0: A block (128x512 fp16) + e2 ----
    #pragma unroll
    for (int i = 0; i < 32; i++) {
        int q = t + i * 256;          // 8192 16B chunks
        int r = q >> 6, c = q & 63;
        uint32_t dst = sA + r * 1024 + (((c ^ (r & 7))) << 4);
        const __half* src = g_Ah + (size_t)(row0 + r) * DIM + c * 8;
        CP16(dst, src);
    }
    #pragma unroll
    for (int i = 0; i < 4; i++) {
        int q = t + i * 256;          // 1024 16B chunks
        uint32_t dst = sbase + SE_OFF + q * 16;
        const float* src = g_e2 + q * 4;
        CP16(dst, src);
    }
    CP_COMMIT();
    // ---- prologue B stages 0..2 ----
    #pragma unroll
    for (int s = 0; s < 3; s++) { load_B(sB, t, s, s); CP_COMMIT(); }

    float v1[8], v2[8]; int i1[8];
    #pragma unroll
    for (int s = 0; s < 8; s++) { v1[s] = FLT_MAX; v2[s] = FLT_MAX; i1[s] = 0; }

    float acc[4][4][4];

    for (int i = 0; i < 256; i++) {
        if (i <= 253)      asm volatile("cp.async.wait_group 2;" ::: "memory");
        else if (i == 254) asm volatile("cp.async.wait_group 1;" ::: "memory");
        else               asm volatile("cp.async.wait_group 0;" ::: "memory");
        __syncthreads();

        const int kk = i & 7, p = i >> 3;
        if (kk == 0) {
            #pragma unroll
            for (int mi = 0; mi < 4; mi++)
                #pragma unroll
                for (int ni = 0; ni < 4; ni++)
                    #pragma unroll
                    for (int q = 0; q < 4; q++) acc[mi][ni][q] = 0.f;
        }
        const uint32_t stg = sB + (i & 3) * 16384;

        #pragma unroll
        for (int s = 0; s < 4; s++) {
            uint32_t a[4][4];
            const int rowA = lane & 15;
            const int ca = kk * 8 + s * 2 + (lane >> 4);
            #pragma unroll
            for (int mi = 0; mi < 4; mi++) {
                int rg = wr * 64 + mi * 16 + rowA;
                uint32_t ad = sA + rg * 1024 + (((ca ^ (rg & 7))) << 4);
                LDSM4(a[mi], ad);
            }
            uint32_t b[2][4];
            const int nl = ((lane >> 4) << 3) + (lane & 7);
            const int cb = s * 2 + ((lane >> 3) & 1);
            #pragma unroll
            for (int np = 0; np < 2; np++) {
                int ng = wc * 32 + np * 16 + nl;
                uint32_t bd = stg + ng * 128 + (((cb ^ (ng & 7))) << 4);
                LDSM4(b[np], bd);
            }
            #pragma unroll
            for (int mi = 0; mi < 4; mi++)
                #pragma unroll
                for (int ni = 0; ni < 4; ni++)
                    MMA16(acc[mi][ni], a[mi], b[ni >> 1][(ni & 1) * 2],
                          b[ni >> 1][(ni & 1) * 2 + 1]);
        }

        if (kk == 7) {
            // dist = e2[col] - 2*dot ; update per-row top-2
            #pragma unroll
            for (int mi = 0; mi < 4; mi++) {
                #pragma unroll
                for (int ni = 0; ni < 4; ni++) {
                    int col = p * 128 + wc * 32 + ni * 8 + (lane & 3) * 2;
                    float ea = e2p[col], eb = e2p[col + 1];
                    float d0 = fmaf(-2.f, acc[mi][ni][0], ea);
                    float d1 = fmaf(-2.f, acc[mi][ni][1], eb);
                    float d2 = fmaf(-2.f, acc[mi][ni][2], ea);
                    float d3 = fmaf(-2.f, acc[mi][ni][3], eb);
                    int s0 = mi * 2, s1 = mi * 2 + 1;
                    if (d0 < v1[s0]) { v2[s0] = v1[s0]; v1[s0] = d0; i1[s0] = col; }
                    else if (d0 < v2[s0]) v2[s0] = d0;
                    if (d1 < v1[s0]) { v2[s0] = v1[s0]; v1[s0] = d1; i1[s0] = col + 1; }
                    else if (d1 < v2[s0]) v2[s0] = d1;
                    if (d2 < v1[s1]) { v2[s1] = v1[s1]; v1[s1] = d2; i1[s1] = col; }
                    else if (d2 < v2[s1]) v2[s1] = d2;
                    if (d3 < v1[s1]) { v2[s1] = v1[s1]; v1[s1] = d3; i1[s1] = col + 1; }
                    else if (d3 < v2[s1]) v2[s1] = d3;
                }
            }
        }
        int nx = i + 3;
        if (nx < 256) { load_B(sB, t, nx & 3, nx); CP_COMMIT(); }
    }

    // ---- intra-warp merge (4 lanes share each row) ----
    #pragma unroll
    for (int s = 0; s < 8; s++) {
        #pragma unroll
        for (int off = 1; off <= 2; off <<= 1) {
            float ov1 = __shfl_xor_sync(0xffffffffu, v1[s], off);
            int   oi1 = __shfl_xor_sync(0xffffffffu, i1[s], off);
            float ov2 = __shfl_xor_sync(0xffffffffu, v2[s], off);
            if (ov1 < v1[s] || (ov1 == v1[s] && oi1 < i1[s])) {
                v2[s] = fminf(v1[s], ov2);
                v1[s] = ov1; i1[s] = oi1;
            } else {
                v2[s] = fminf(v2[s], ov1);
            }
        }
    }
    __syncthreads();   // all compute & cp.async done; reuse B-stage SMEM
    float* mv1 = (float*)(smem + SB_OFF);
    int*   mi1 = (int*)(smem + SB_OFF + 2048);
    float* mv2 = (float*)(smem + SB_OFF + 4096);
    if ((lane & 3) == 0) {
        #pragma unroll
        for (int s = 0; s < 8; s++) {
            int m = s >> 1, h = s & 1;
            int r = wr * 64 + m * 16 + h * 8 + (lane >> 2);
            mv1[r * 4 + wc] = v1[s];
            mi1[r * 4 + wc] = i1[s];
            mv2[r * 4 + wc] = v2[s];
        }
    }
    __syncthreads();
    if (t < 128) {
        float bv = mv1[t * 4], bv2 = mv2[t * 4];
        int bi = mi1[t * 4];
        #pragma unroll
        for (int w = 1; w < 4; w++) {
            float ov1 = mv1[t * 4 + w], ov2 = mv2[t * 4 + w];
            int oi = mi1[t * 4 + w];
            if (ov1 < bv || (ov1 == bv && oi < bi)) {
                bv2 = fminf(bv, ov2); bv = ov1; bi = oi;
            } else {
                bv2 = fminf(bv2, ov1);
            }
        }
        g_best[row0 + t] = bi;
        g_margin[row0 + t] = bv2 - bv;
    }
}

// ---------------- rescue: compact + exact fp32 rescore ----------------
__global__ void compact_kernel() {
    int r = blockIdx.x * blockDim.x + threadIdx.x;
    if (r < NROWS && g_margin[r] < THRESH) {
        int p = atomicAdd(&g_cnt, 1);
        g_list[p] = r;
    }
}

// 8 rows per block share the embT stream; warp-per-code, coalesced.
__global__ __launch_bounds__(256) void rescore_kernel(const float* __restrict__ x) {
    __shared__ float xs[8][DIM];
    __shared__ float wv[8][8];
    __shared__ int   wi[8][8];
    __shared__ int   rows[8];
    const int n = g_cnt;
    const int t = threadIdx.x, w = t >> 5, lane = t & 31;

    for (int g = blockIdx.x; g * 8 < n; g += gridDim.x) {
        __syncthreads();
        if (t < 8) rows[t] = (g * 8 + t < n) ? g_list[g * 8 + t] : -1;
        __syncthreads();
        for (int idx = t; idx < 8 * DIM; idx += 256) {
            int r = idx >> 9, d = idx & 511;
            int rr = rows[r] >= 0 ? rows[r] : rows[0];
            xs[r][d] = x[(size_t)rr * DIM + d];
        }
        __syncthreads();

        float bv[8]; int bi[8];
        #pragma unroll
        for (int r = 0; r < 8; r++) { bv[r] = FLT_MAX; bi[r] = 0; }

        for (int j = w; j < NE; j += 8) {
            const float4* er = (const float4*)(g_embT + (size_t)j * DIM);
            float a[8];
            #pragma unroll
            for (int r = 0; r < 8; r++) a[r] = 0.f;
            #pragma unroll
            for (int sub = 0; sub < 4; sub++) {
                float4 e = er[sub * 32 + lane];
                #pragma unroll
                for (int r = 0; r < 8; r++) {
                    const float4 xv = *(const float4*)&xs[r][sub * 128 + lane * 4];
                    a[r] = fmaf(e.x, xv.x, a[r]);
                    a[r] = fmaf(e.y, xv.y, a[r]);
                    a[r] = fmaf(e.z, xv.z, a[r]);
                    a[r] = fmaf(e.w, xv.w, a[r]);
                }
            }
            #pragma unroll
            for (int r = 0; r < 8; r++)
                #pragma unroll
                for (int o = 16; o > 0; o >>= 1)
                    a[r] += __shfl_xor_sync(0xffffffffu, a[r], o);
            float e2 = g_e2[j];
            #pragma unroll
            for (int r = 0; r < 8; r++) {
                float d = fmaf(-2.f, a[r], e2);
                if (d < bv[r]) { bv[r] = d; bi[r] = j; }
            }
        }
        if (lane == 0) {
            #pragma unroll
            for (int r = 0; r < 8; r++) { wv[w][r] = bv[r]; wi[w][r] = bi[r]; }
        }
        __syncthreads();
        if (t < 8) {
            int r = t;
            float fb = wv[0][r]; int fi = wi[0][r];
            #pragma unroll
            for (int q = 1; q < 8; q++) {
                if (wv[q][r] < fb || (wv[q][r] == fb && wi[q][r] < fi)) {
                    fb = wv[q][r]; fi = wi[q][r];
                }
            }
            if (g * 8 + r < n) g_best[rows[r]] = fi;
        }
    }
}

// ---------------- gather + diff ----------------
__global__ __launch_bounds__(128) void gather_kernel(
    const float* __restrict__ x, float* __restrict__ out)
{
    const int row = blockIdx.x;
    const int t = threadIdx.x;
    const int idx = g_best[row];
    const float4* q4 = (const float4*)(g_embT + (size_t)idx * DIM);
    const float4* x4 = (const float4*)(x + (size_t)row * DIM);
    float4* o4 = (float4*)(out + (size_t)row * DIM);

    float4 q = q4[t];
    float4 xv = x4[t];
    float dx = q.x - xv.x, dy = q.y - xv.y, dz = q.z - xv.z, dw = q.w - xv.w;
    float4 o;
    o.x = xv.x + dx; o.y = xv.y + dy; o.z = xv.z + dz; o.w = xv.w + dw;
    o4[t] = o;
    float s = dx * dx + dy * dy + dz * dz + dw * dw;

    __shared__ float red[128];
    red[t] = s;
    __syncthreads();
    #pragma unroll
    for (int off = 64; off > 0; off >>= 1) {
        if (t < off) red[t] += red[t + off];
        __syncthreads();
    }
    if (t == 0) {
        g_partial[row] = red[0];
        out[(size_t)NROWS * DIM + 1 + row] = (float)idx;
    }
}

__global__ void final_kernel(float* __restrict__ out) {
    __shared__ double red[256];
    int t = threadIdx.x;
    double s = 0.0;
    for (int i = t; i < NROWS; i += 256) s += (double)g_partial[i];
    red[t] = s;
    __syncthreads();
    for (int off = 128; off > 0; off >>= 1) {
        if (t < off) red[t] += red[t + off];
        __syncthreads();
    }
    if (t == 0)
        out[(size_t)NROWS * DIM] = (float)(red[0] / ((double)NROWS * (double)DIM));
}

// ----------------------------------------------------------------
extern "C" void kernel_launch(void* const* d_in, const int* in_sizes, int n_in,
                              void* d_out, int out_size) {
    const float* x     = (const float*)d_in[0];
    const float* embed = (const float*)d_in[1];
    float* out = (float*)d_out;

    cudaFuncSetAttribute(gemm_argmin_kernel,
                         cudaFuncAttributeMaxDynamicSharedMemorySize, SMEM_SZ);

    pack_x_kernel<<<NROWS * DIM / 4 / 256, 256>>>(x);
    pack_embed_kernel<<<dim3(NE / 32, DIM / 32), dim3(32, 8)>>>(embed);
    prep_e2<<<NE / 256, 256>>>(embed);
    gemm_argmin_kernel<<<NROWS / 128, 256, SMEM_SZ>>>();
    compact_kernel<<<NROWS / 256, 256>>>();
    rescore_kernel<<<256, 256>>>(x);
    gather_kernel<<<NROWS, 128>>>(x, out);
    final_kernel<<<1, 256>>>(out);
}

// round 9
// speedup vs baseline: 2.5156x; 1.0152x over previous
#include <cuda_runtime.h>
#include <cuda_fp16.h>
#include <cstdint>
#include <cfloat>

#define DIM    512
#define NE     4096
#define NROWS  65536
#define THRESH 0.35f

// ---------------- scratch (__device__ globals) ----------------
__device__ __align__(128) __half g_Ah[(size_t)NROWS * DIM];  // x as fp16
__device__ __align__(128) __half g_Bh[(size_t)NE * DIM];     // embT as fp16
__device__ float g_embT[(size_t)NE * DIM];
__device__ float g_e2[NE];
__device__ int   g_best[NROWS];
__device__ float g_margin[NROWS];
__device__ float g_partial[NROWS];
__device__ int   g_list[NROWS];
__device__ int   g_cnt;

// ---------------- asm helpers ----------------
__device__ __forceinline__ uint32_t smem_u32(const void* p) {
    uint32_t a;
    asm("{ .reg .u64 t; cvta.to.shared.u64 t, %1; cvt.u32.u64 %0, t; }" : "=r"(a) : "l"(p));
    return a;
}
#define CP16(dst, src) \
    asm volatile("cp.async.cg.shared.global [%0], [%1], 16;" :: "r"(dst), "l"(src))
#define CP_COMMIT() asm volatile("cp.async.commit_group;" ::: "memory")

#define LDSM4(r, addr) \
    asm volatile("ldmatrix.sync.aligned.m8n8.x4.shared.b16 {%0,%1,%2,%3}, [%4];" \
        : "=r"((r)[0]), "=r"((r)[1]), "=r"((r)[2]), "=r"((r)[3]) : "r"(addr))

#define MMA16(c, a, b0, b1) \
    asm volatile("mma.sync.aligned.m16n8k16.row.col.f32.f16.f16.f32 " \
        "{%0,%1,%2,%3},{%4,%5,%6,%7},{%8,%9},{%0,%1,%2,%3};" \
        : "+f"((c)[0]), "+f"((c)[1]), "+f"((c)[2]), "+f"((c)[3]) \
        : "r"((a)[0]), "r"((a)[1]), "r"((a)[2]), "r"((a)[3]), "r"(b0), "r"(b1))

// ---------------- prep: pack x -> fp16 ----------------
__global__ __launch_bounds__(256) void pack_x_kernel(const float* __restrict__ x) {
    size_t g = (size_t)blockIdx.x * 256 + threadIdx.x;
    if (g == 0) g_cnt = 0;
    size_t e = g * 4;
    float4 v = *(const float4*)(x + e);
    __half2 h0 = __floats2half2_rn(v.x, v.y);
    __half2 h1 = __floats2half2_rn(v.z, v.w);
    uint2 pk;
    pk.x = *(uint32_t*)&h0;
    pk.y = *(uint32_t*)&h1;
    *(uint2*)(g_Ah + e) = pk;
}

// ---------------- prep: transpose embed -> fp16 B + fp32 embT ----------------
__global__ void pack_embed_kernel(const float* __restrict__ embed) {
    __shared__ float tile[32][33];
    int jb = blockIdx.x * 32;
    int db = blockIdx.y * 32;
    int tx = threadIdx.x, ty = threadIdx.y;  // 32 x 8
    #pragma unroll
    for (int d = ty; d < 32; d += 8)
        tile[d][tx] = embed[(size_t)(db + d) * NE + jb + tx];
    __syncthreads();
    #pragma unroll
    for (int j = ty; j < 32; j += 8) {
        float v = tile[tx][j];
        size_t o = (size_t)(jb + j) * DIM + db + tx;
        g_Bh[o]   = __float2half_rn(v);
        g_embT[o] = v;
    }
}

__global__ void prep_e2(const float* __restrict__ embed) {
    int j = blockIdx.x * blockDim.x + threadIdx.x;
    if (j < NE) {
        float s = 0.f;
        #pragma unroll 8
        for (int d = 0; d < DIM; d++) {
            float v = embed[(size_t)d * NE + j];
            s = fmaf(v, v, s);
        }
        g_e2[j] = s;
    }
}

// ---------------- GEMM + argmin (mma.sync fp16, 512 threads) --------
// SMEM layout (dynamic, 212992 B):
//   [0, 131072)        A block 128 x 512 fp16, swizzled
//   [131072, 196608)   B stages: 4 x 16384 (128n x 64k fp16, swizzled)
//                      (reused post-loop as merge buffer)
//   [196608, 212992)   e2[4096] fp32
#define SA_OFF 0
#define SB_OFF 131072
#define SE_OFF 196608
#define SMEM_SZ 212992
#define NT 512

__device__ __forceinline__ void load_B(uint32_t sB, int t, int slot, int idx) {
    const int col0 = (idx >> 3) << 7;
    const int kk = idx & 7;
    const __half* base = g_Bh + (size_t)col0 * DIM + kk * 64;
    uint32_t sbase = sB + slot * 16384;
    #pragma unroll
    for (int i = 0; i < 2; i++) {
        int q = t + i * NT;
        int n = q >> 3, ck = q & 7;
        uint32_t dst = sbase + n * 128 + (((ck ^ (n & 7))) << 4);
        const __half* src = base + (size_t)n * DIM + ck * 8;
        CP16(dst, src);
    }
}

__global__ __launch_bounds__(NT, 1) void gemm_argmin_kernel() {
    extern __shared__ __align__(128) char smem[];
    const uint32_t sbase = smem_u32(smem);
    const uint32_t sA = sbase + SA_OFF;
    const uint32_t sB = sbase + SB_OFF;
    const int t = threadIdx.x;
    const int lane = t & 31, warp = t >> 5;
    const int wr = warp >> 2, wc = warp & 3;      // 4 x 4 warp grid
    const int row0 = blockIdx.x * 128;
    float* e2p = (float*)(smem + SE_OFF);

    // ---- group 0: A block (128x512 fp16) + e2 ----
    #pragma unroll
    for (int i = 0; i < 16; i++) {
        int q = t + i * NT;           // 8192 16B chunks
        int r = q >> 6, c = q & 63;
        uint32_t dst = sA + r * 1024 + (((c ^ (r & 7))) << 4);
        const __half* src = g_Ah + (size_t)(row0 + r) * DIM + c * 8;
        CP16(dst, src);
    }
    #pragma unroll
    for (int i = 0; i < 2; i++) {
        int q = t + i * NT;           // 1024 16B chunks
        uint32_t dst = sbase + SE_OFF + q * 16;
        const float* src = g_e2 + q * 4;
        CP16(dst, src);
    }
    CP_COMMIT();
    // ---- prologue B stages 0..2 ----
    #pragma unroll
    for (int s = 0; s < 3; s++) { load_B(sB, t, s, s); CP_COMMIT(); }

    float v1[4], v2[4]; int i1[4];
    #pragma unroll
    for (int s = 0; s < 4; s++) { v1[s] = FLT_MAX; v2[s] = FLT_MAX; i1[s] = 0; }

    float acc[2][4][4];

    for (int i = 0; i < 256; i++) {
        if (i <= 253)      asm volatile("cp.async.wait_group 2;" ::: "memory");
        else if (i == 254) asm volatile("cp.async.wait_group 1;" ::: "memory");
        else               asm volatile("cp.async.wait_group 0;" ::: "memory");
        __syncthreads();

        const int kk = i & 7, p = i >> 3;
        if (kk == 0) {
            #pragma unroll
            for (int mi = 0; mi < 2; mi++)
                #pragma unroll
                for (int ni = 0; ni < 4; ni++)
                    #pragma unroll
                    for (int q = 0; q < 4; q++) acc[mi][ni][q] = 0.f;
        }
        const uint32_t stg = sB + (i & 3) * 16384;

        #pragma unroll
        for (int s = 0; s < 4; s++) {
            uint32_t a[2][4];
            const int rowA = lane & 15;
            const int ca = kk * 8 + s * 2 + (lane >> 4);
            #pragma unroll
            for (int mi = 0; mi < 2; mi++) {
                int rg = wr * 32 + mi * 16 + rowA;
                uint32_t ad = sA + rg * 1024 + (((ca ^ (rg & 7))) << 4);
                LDSM4(a[mi], ad);
            }
            uint32_t b[2][4];
            const int nl = ((lane >> 4) << 3) + (lane & 7);
            const int cb = s * 2 + ((lane >> 3) & 1);
            #pragma unroll
            for (int np = 0; np < 2; np++) {
                int ng = wc * 32 + np * 16 + nl;
                uint32_t bd = stg + ng * 128 + (((cb ^ (ng & 7))) << 4);
                LDSM4(b[np], bd);
            }
            #pragma unroll
            for (int mi = 0; mi < 2; mi++)
                #pragma unroll
                for (int ni = 0; ni < 4; ni++)
                    MMA16(acc[mi][ni], a[mi], b[ni >> 1][(ni & 1) * 2],
                          b[ni >> 1][(ni & 1) * 2 + 1]);
        }

        if (kk == 7) {
            // dist = e2[col] - 2*dot ; update per-row top-2
            #pragma unroll
            for (int mi = 0; mi < 2; mi++) {
                #pragma unroll
                for (int ni = 0; ni < 4; ni++) {
                    int col = p * 128 + wc * 32 + ni * 8 + (lane & 3) * 2;
                    float ea = e2p[col], eb = e2p[col + 1];
                    float d0 = fmaf(-2.f, acc[mi][ni][0], ea);
                    float d1 = fmaf(-2.f, acc[mi][ni][1], eb);
                    float d2 = fmaf(-2.f, acc[mi][ni][2], ea);
                    float d3 = fmaf(-2.f, acc[mi][ni][3], eb);
                    int s0 = mi * 2, s1 = mi * 2 + 1;
                    if (d0 < v1[s0]) { v2[s0] = v1[s0]; v1[s0] = d0; i1[s0] = col; }
                    else if (d0 < v2[s0]) v2[s0] = d0;
                    if (d1 < v1[s0]) { v2[s0] = v1[s0]; v1[s0] = d1; i1[s0] = col + 1; }
                    else if (d1 < v2[s0]) v2[s0] = d1;
                    if (d2 < v1[s1]) { v2[s1] = v1[s1]; v1[s1] = d2; i1[s1] = col; }
                    else if (d2 < v2[s1]) v2[s1] = d2;
                    if (d3 < v1[s1]) { v2[s1] = v1[s1]; v1[s1] = d3; i1[s1] = col + 1; }
                    else if (d3 < v2[s1]) v2[s1] = d3;
                }
            }
        }
        int nx = i + 3;
        if (nx < 256) { load_B(sB, t, nx & 3, nx); CP_COMMIT(); }
    }

    // ---- intra-warp merge (4 lanes share each row) ----
    #pragma unroll
    for (int s = 0; s < 4; s++) {
        #pragma unroll
        for (int off = 1; off <= 2; off <<= 1) {
            float ov1 = __shfl_xor_sync(0xffffffffu, v1[s], off);
            int   oi1 = __shfl_xor_sync(0xffffffffu, i1[s], off);
            float ov2 = __shfl_xor_sync(0xffffffffu, v2[s], off);
            if (ov1 < v1[s] || (ov1 == v1[s] && oi1 < i1[s])) {
                v2[s] = fminf(v1[s], ov2);
                v1[s] = ov1; i1[s] = oi1;
            } else {
                v2[s] = fminf(v2[s], ov1);
            }
        }
    }
    __syncthreads();   // all compute & cp.async done; reuse B-stage SMEM
    float* mv1 = (float*)(smem + SB_OFF);
    int*   mi1 = (int*)(smem + SB_OFF + 2048);
    float* mv2 = (float*)(smem + SB_OFF + 4096);
    if ((lane & 3) == 0) {
        #pragma unroll
        for (int s = 0; s < 4; s++) {
            int m = s >> 1, h = s & 1;
            int r = wr * 32 + m * 16 + h * 8 + (lane >> 2);
            mv1[r * 4 + wc] = v1[s];
            mi1[r * 4 + wc] = i1[s];
            mv2[r * 4 + wc] = v2[s];
        }
    }
    __syncthreads();
    if (t < 128) {
        float bv = mv1[t * 4], bv2 = mv2[t * 4];
        int bi = mi1[t * 4];
        #pragma unroll
        for (int w = 1; w < 4; w++) {
            float ov1 = mv1[t * 4 + w], ov2 = mv2[t * 4 + w];
            int oi = mi1[t * 4 + w];
            if (ov1 < bv || (ov1 == bv && oi < bi)) {
                bv2 = fminf(bv, ov2); bv = ov1; bi = oi;
            } else {
                bv2 = fminf(bv2, ov1);
            }
        }
        g_best[row0 + t] = bi;
        g_margin[row0 + t] = bv2 - bv;
    }
}

// ---------------- rescue: compact + exact fp32 rescore ----------------
__global__ void compact_kernel() {
    int r = blockIdx.x * blockDim.x + threadIdx.x;
    if (r < NROWS && g_margin[r] < THRESH) {
        int p = atomicAdd(&g_cnt, 1);
        g_list[p] = r;
    }
}

// 8 rows per block share the embT stream; warp-per-code, coalesced.
__global__ __launch_bounds__(256) void rescore_kernel(const float* __restrict__ x) {
    __shared__ float xs[8][DIM];
    __shared__ float wv[8][8];
    __shared__ int   wi[8][8];
    __shared__ int   rows[8];
    const int n = g_cnt;
    const int t = threadIdx.x, w = t >> 5, lane = t & 31;

    for (int g = blockIdx.x; g * 8 < n; g += gridDim.x) {
        __syncthreads();
        if (t < 8) rows[t] = (g * 8 + t < n) ? g_list[g * 8 + t] : -1;
        __syncthreads();
        for (int idx = t; idx < 8 * DIM; idx += 256) {
            int r = idx >> 9, d = idx & 511;
            int rr = rows[r] >= 0 ? rows[r] : rows[0];
            xs[r][d] = x[(size_t)rr * DIM + d];
        }
        __syncthreads();

        float bv[8]; int bi[8];
        #pragma unroll
        for (int r = 0; r < 8; r++) { bv[r] = FLT_MAX; bi[r] = 0; }

        for (int j = w; j < NE; j += 8) {
            const float4* er = (const float4*)(g_embT + (size_t)j * DIM);
            float a[8];
            #pragma unroll
            for (int r = 0; r < 8; r++) a[r] = 0.f;
            #pragma unroll
            for (int sub = 0; sub < 4; sub++) {
                float4 e = er[sub * 32 + lane];
                #pragma unroll
                for (int r = 0; r < 8; r++) {
                    const float4 xv = *(const float4*)&xs[r][sub * 128 + lane * 4];
                    a[r] = fmaf(e.x, xv.x, a[r]);
                    a[r] = fmaf(e.y, xv.y, a[r]);
                    a[r] = fmaf(e.z, xv.z, a[r]);
                    a[r] = fmaf(e.w, xv.w, a[r]);
                }
            }
            #pragma unroll
            for (int r = 0; r < 8; r++)
                #pragma unroll
                for (int o = 16; o > 0; o >>= 1)
                    a[r] += __shfl_xor_sync(0xffffffffu, a[r], o);
            float e2 = g_e2[j];
            #pragma unroll
            for (int r = 0; r < 8; r++) {
                float d = fmaf(-2.f, a[r], e2);
                if (d < bv[r]) { bv[r] = d; bi[r] = j; }
            }
        }
        if (lane == 0) {
            #pragma unroll
            for (int r = 0; r < 8; r++) { wv[w][r] = bv[r]; wi[w][r] = bi[r]; }
        }
        __syncthreads();
        if (t < 8) {
            int r = t;
            float fb = wv[0][r]; int fi = wi[0][r];
            #pragma unroll
            for (int q = 1; q < 8; q++) {
                if (wv[q][r] < fb || (wv[q][r] == fb && wi[q][r] < fi)) {
                    fb = wv[q][r]; fi = wi[q][r];
                }
            }
            if (g * 8 + r < n) g_best[rows[r]] = fi;
        }
    }
}

// ---------------- gather + diff ----------------
__global__ __launch_bounds__(128) void gather_kernel(
    const float* __restrict__ x, float* __restrict__ out)
{
    const int row = blockIdx.x;
    const int t = threadIdx.x;
    const int idx = g_best[row];
    const float4* q4 = (const float4*)(g_embT + (size_t)idx * DIM);
    const float4* x4 = (const float4*)(x + (size_t)row * DIM);
    float4* o4 = (float4*)(out + (size_t)row * DIM);

    float4 q = q4[t];
    float4 xv = x4[t];
    float dx = q.x - xv.x, dy = q.y - xv.y, dz = q.z - xv.z, dw = q.w - xv.w;
    float4 o;
    o.x = xv.x + dx; o.y = xv.y + dy; o.z = xv.z + dz; o.w = xv.w + dw;
    o4[t] = o;
    float s = dx * dx + dy * dy + dz * dz + dw * dw;

    __shared__ float red[128];
    red[t] = s;
    __syncthreads();
    #pragma unroll
    for (int off = 64; off > 0; off >>= 1) {
        if (t < off) red[t] += red[t + off];
        __syncthreads();
    }
    if (t == 0) {
        g_partial[row] = red[0];
        out[(size_t)NROWS * DIM + 1 + row] = (float)idx;
    }
}

__global__ void final_kernel(float* __restrict__ out) {
    __shared__ double red[256];
    int t = threadIdx.x;
    double s = 0.0;
    for (int i = t; i < NROWS; i += 256) s += (double)g_partial[i];
    red[t] = s;
    __syncthreads();
    for (int off = 128; off > 0; off >>= 1) {
        if (t < off) red[t] += red[t + off];
        __syncthreads();
    }
    if (t == 0)
        out[(size_t)NROWS * DIM] = (float)(red[0] / ((double)NROWS * (double)DIM));
}

// ----------------------------------------------------------------
extern "C" void kernel_launch(void* const* d_in, const int* in_sizes, int n_in,
                              void* d_out, int out_size) {
    const float* x     = (const float*)d_in[0];
    const float* embed = (const float*)d_in[1];
    float* out = (float*)d_out;

    cudaFuncSetAttribute(gemm_argmin_kernel,
                         cudaFuncAttributeMaxDynamicSharedMemorySize, SMEM_SZ);

    pack_x_kernel<<<NROWS * DIM / 4 / 256, 256>>>(x);
    pack_embed_kernel<<<dim3(NE / 32, DIM / 32), dim3(32, 8)>>>(embed);
    prep_e2<<<NE / 256, 256>>>(embed);
    gemm_argmin_kernel<<<NROWS / 128, NT, SMEM_SZ>>>();
    compact_kernel<<<NROWS / 256, 256>>>();
    rescore_kernel<<<256, 256>>>(x);
    gather_kernel<<<NROWS, 128>>>(x, out);
    final_kernel<<<1, 256>>>(out);
}